// round 1
// baseline (speedup 1.0000x reference)
#include <cuda_runtime.h>
#include <cuda_bf16.h>

#define N_PP 8192
#define N_AP 16384
#define DIM  16
#define BM   256        // rows per block (1 per thread)
#define BN   128        // cols per block

// accumulators: 0 = nonlink_pp, 1 = link_pp, 2 = nonlink_ap, 3 = link_ap
__device__ double g_acc[4];

__device__ __forceinline__ float fast_sqrt(float x) {
    float r; asm("sqrt.approx.f32 %0, %1;" : "=f"(r) : "f"(x)); return r;
}

__global__ void zero_acc_kernel() {
    if (threadIdx.x < 4) g_acc[threadIdx.x] = 0.0;
}

// block reduce: returns valid sum on thread 0
__device__ __forceinline__ float block_reduce(float v, float* sh) {
    #pragma unroll
    for (int off = 16; off > 0; off >>= 1)
        v += __shfl_down_sync(0xffffffffu, v, off);
    int lane = threadIdx.x & 31;
    int w = threadIdx.x >> 5;
    if (lane == 0) sh[w] = v;
    __syncthreads();
    if (w == 0) {
        v = (lane < (int)(blockDim.x >> 5)) ? sh[lane] : 0.f;
        #pragma unroll
        for (int off = 4; off > 0; off >>= 1)
            v += __shfl_down_sync(0xffffffffu, v, off);
    }
    return v;
}

// Pairwise nonlink terms. Virtual column space: cb in [0,64) -> pp cols (p),
// cb in [64,128) -> ap cols (a). Rows are always p_star.
__global__ __launch_bounds__(BM) void pair_kernel(
    const float* __restrict__ p_star,
    const float* __restrict__ p,
    const float* __restrict__ a,
    const float* __restrict__ beta,
    const float* __restrict__ gamma)
{
    __shared__ float ys[BN * DIM];   // col embeddings
    __shared__ float yn[BN];         // ||y||^2
    __shared__ float yw[BN];         // exp(col weight)
    __shared__ float red[8];

    const int cb = blockIdx.x;               // 0..127
    const int rb = blockIdx.y;               // 0..31
    const bool is_pp = (cb < (N_PP / BN));
    const int row0 = rb * BM;
    const int col0 = (is_pp ? cb : cb - (N_PP / BN)) * BN;

    // pp strict upper triangle: block has work iff max col (col0+BN-1) > min row
    if (is_pp && (col0 + BN - 1) <= row0) return;

    const int tid = threadIdx.x;
    const float* ysrc = is_pp ? p : a;

    // stage column tile (128 x 16 floats) via float4
    {
        const float4* src = reinterpret_cast<const float4*>(ysrc + (size_t)col0 * DIM);
        float4* dst = reinterpret_cast<float4*>(ys);
        #pragma unroll
        for (int idx = tid; idx < BN * DIM / 4; idx += BM)
            dst[idx] = src[idx];
    }
    __syncthreads();
    // col norms + weights
    for (int j = tid; j < BN; j += BM) {
        int gj = col0 + j;
        float w = is_pp ? gamma[gj + N_PP] : beta[N_PP + gj];
        yw[j] = __expf(w);
        const float* yr = ys + j * DIM;
        float s = 0.f;
        #pragma unroll
        for (int k = 0; k < DIM; k++) s += yr[k] * yr[k];
        yn[j] = s;
    }
    __syncthreads();

    // this thread's row
    const int r = row0 + tid;
    const float4* xr = reinterpret_cast<const float4*>(p_star + (size_t)r * DIM);
    float4 x0 = xr[0], x1 = xr[1], x2 = xr[2], x3 = xr[3];
    float xn =
        x0.x*x0.x + x0.y*x0.y + x0.z*x0.z + x0.w*x0.w +
        x1.x*x1.x + x1.y*x1.y + x1.z*x1.z + x1.w*x1.w +
        x2.x*x2.x + x2.y*x2.y + x2.z*x2.z + x2.w*x2.w +
        x3.x*x3.x + x3.y*x3.y + x3.z*x3.z + x3.w*x3.w;
    float rowexp = __expf(is_pp ? gamma[r] : beta[r]);

    float acc = 0.f;
    #pragma unroll 4
    for (int j = 0; j < BN; j++) {
        const float4* yv = reinterpret_cast<const float4*>(ys + j * DIM);
        float4 y0 = yv[0], y1 = yv[1], y2 = yv[2], y3 = yv[3];
        float d0 = x0.x*y0.x + x0.y*y0.y + x0.z*y0.z + x0.w*y0.w;
        float d1 = x1.x*y1.x + x1.y*y1.y + x1.z*y1.z + x1.w*y1.w;
        float d2s = x2.x*y2.x + x2.y*y2.y + x2.z*y2.z + x2.w*y2.w;
        float d3 = x3.x*y3.x + x3.y*y3.y + x3.z*y3.z + x3.w*y3.w;
        float dot = (d0 + d1) + (d2s + d3);
        float dist2 = fmaf(-2.f, dot, xn + yn[j]);
        float dist = fast_sqrt(fmaxf(dist2, 0.f));
        float t = yw[j] * __expf(-dist);
        if (is_pp && (col0 + j) <= r) t = 0.f;   // strict upper triangle
        acc += t;
    }
    acc *= rowexp;

    float bsum = block_reduce(acc, red);
    if (tid == 0)
        atomicAdd(&g_acc[is_pp ? 0 : 2], (double)bsum);
}

// Link terms over edges (one thread per edge, both edge sets)
__global__ __launch_bounds__(256) void edge_kernel(
    const float* __restrict__ p_star,
    const float* __restrict__ p,
    const float* __restrict__ a,
    const float* __restrict__ beta,
    const float* __restrict__ gamma,
    const int* __restrict__ e_pp,
    const int* __restrict__ e_ap,
    int E)
{
    __shared__ float red[8];
    int i = blockIdx.x * blockDim.x + threadIdx.x;
    float acc_pp = 0.f, acc_ap = 0.f;
    for (int e = i; e < E; e += gridDim.x * blockDim.x) {
        // ---- pp edge ----
        {
            int s = e_pp[e];
            int t = e_pp[E + e];
            const float4* xs = reinterpret_cast<const float4*>(p_star + (size_t)s * DIM);
            const float4* yt = reinterpret_cast<const float4*>(p + (size_t)t * DIM);
            float d2 = 0.f;
            #pragma unroll
            for (int k = 0; k < 4; k++) {
                float4 xv = xs[k], yv = yt[k];
                float dx = xv.x - yv.x, dy = xv.y - yv.y, dz = xv.z - yv.z, dw = xv.w - yv.w;
                d2 += dx*dx + dy*dy + dz*dz + dw*dw;
            }
            acc_pp += gamma[s] + gamma[t + N_PP] - fast_sqrt(d2);
        }
        // ---- ap edge ----
        {
            int s = e_ap[e];
            int t = e_ap[E + e];           // in [N_PP, N_AP)
            const float4* xs = reinterpret_cast<const float4*>(p_star + (size_t)s * DIM);
            const float4* yt = reinterpret_cast<const float4*>(a + (size_t)(t - N_PP) * DIM);
            float d2 = 0.f;
            #pragma unroll
            for (int k = 0; k < 4; k++) {
                float4 xv = xs[k], yv = yt[k];
                float dx = xv.x - yv.x, dy = xv.y - yv.y, dz = xv.z - yv.z, dw = xv.w - yv.w;
                d2 += dx*dx + dy*dy + dz*dz + dw*dw;
            }
            acc_ap += beta[s] + beta[t] - fast_sqrt(d2);
        }
    }
    float s_pp = block_reduce(acc_pp, red);
    __syncthreads();
    float s_ap = block_reduce(acc_ap, red);
    if (threadIdx.x == 0) {
        atomicAdd(&g_acc[1], (double)s_pp);
        atomicAdd(&g_acc[3], (double)s_ap);
    }
}

__global__ void finalize_kernel(float* out) {
    double nonlink_pp = g_acc[0];
    double link_pp    = g_acc[1];
    double nonlink_ap = g_acc[2];
    double link_ap    = g_acc[3];
    double nll_pp = -(link_pp - nonlink_pp);
    double nll_ap = -(link_ap - nonlink_ap);
    out[0] = (float)(0.5 * nll_pp / (double)N_PP + 0.5 * nll_ap / (double)N_PP);
}

extern "C" void kernel_launch(void* const* d_in, const int* in_sizes, int n_in,
                              void* d_out, int out_size) {
    const float* p_star = (const float*)d_in[0];
    const float* p      = (const float*)d_in[1];
    const float* a      = (const float*)d_in[2];
    const float* beta   = (const float*)d_in[3];
    const float* gamma  = (const float*)d_in[4];
    const int*   e_pp   = (const int*)d_in[5];
    const int*   e_ap   = (const int*)d_in[6];
    int E = in_sizes[5] / 2;

    zero_acc_kernel<<<1, 32>>>();

    dim3 grid(2 * N_PP / BN, N_PP / BM);   // 128 x 32
    pair_kernel<<<grid, BM>>>(p_star, p, a, beta, gamma);

    int eblocks = (E + 255) / 256;
    edge_kernel<<<eblocks, 256>>>(p_star, p, a, beta, gamma, e_pp, e_ap, E);

    finalize_kernel<<<1, 1>>>((float*)d_out);
}

// round 2
// speedup vs baseline: 1.0081x; 1.0081x over previous
#include <cuda_runtime.h>
#include <cuda_bf16.h>

#define N_PP 8192
#define N_AP 16384
#define DIM  16
#define BM   256        // rows per block (1 per thread)
#define BN   128        // cols per block
#define L2E  1.4426950408889634f

// accumulators: 0 = nonlink_pp, 1 = link_pp, 2 = nonlink_ap, 3 = link_ap
__device__ double g_acc[4];

__device__ __forceinline__ float fast_sqrt(float x) {
    float r; asm("sqrt.approx.f32 %0, %1;" : "=f"(r) : "f"(x)); return r;
}
__device__ __forceinline__ float fast_exp2(float x) {
    float r; asm("ex2.approx.f32 %0, %1;" : "=f"(r) : "f"(x)); return r;
}
__device__ __forceinline__ unsigned long long pack2(float lo, float hi) {
    unsigned long long r;
    asm("mov.b64 %0, {%1, %2};" : "=l"(r) : "f"(lo), "f"(hi));
    return r;
}
__device__ __forceinline__ void unpack2(unsigned long long v, float& lo, float& hi) {
    asm("mov.b64 {%0, %1}, %2;" : "=f"(lo), "=f"(hi) : "l"(v));
}
__device__ __forceinline__ unsigned long long fma2(unsigned long long a,
                                                   unsigned long long b,
                                                   unsigned long long c) {
    unsigned long long d;
    asm("fma.rn.f32x2 %0, %1, %2, %3;" : "=l"(d) : "l"(a), "l"(b), "l"(c));
    return d;
}

__global__ void zero_acc_kernel() {
    if (threadIdx.x < 4) g_acc[threadIdx.x] = 0.0;
}

__device__ __forceinline__ float block_reduce(float v, float* sh) {
    #pragma unroll
    for (int off = 16; off > 0; off >>= 1)
        v += __shfl_down_sync(0xffffffffu, v, off);
    int lane = threadIdx.x & 31;
    int w = threadIdx.x >> 5;
    if (lane == 0) sh[w] = v;
    __syncthreads();
    if (w == 0) {
        v = (lane < (int)(blockDim.x >> 5)) ? sh[lane] : 0.f;
        #pragma unroll
        for (int off = 4; off > 0; off >>= 1)
            v += __shfl_down_sync(0xffffffffu, v, off);
    }
    return v;
}

// Pairwise nonlink terms. Rows: p_star. Cols: p (IS_PP) or a (!IS_PP).
// Packed f32x2 math: per-thread row pre-scaled by -2, chain initializers
// carry xn and yn so the 8 packed FMAs directly produce dist^2.
template <bool IS_PP>
__global__ __launch_bounds__(BM) void pair_kernel(
    const float* __restrict__ p_star,
    const float* __restrict__ ysrc,      // p or a
    const float* __restrict__ wsrc,      // gamma or beta
    int col_w_off)                       // offset for column weights
{
    __shared__ float4 ys4[BN * 4];       // col embeddings (16 floats each)
    __shared__ float2 meta[BN];          // (yn[j], lw[j]=w*log2e)
    __shared__ float red[8];

    const int cb = blockIdx.x;
    const int rb = blockIdx.y;
    const int row0 = rb * BM;
    const int col0 = cb * BN;

    // pp strict upper triangle: skip blocks entirely at/below diagonal
    if (IS_PP && (col0 + BN - 1) <= row0) return;

    const int tid = threadIdx.x;

    // stage column tile
    {
        const float4* src = reinterpret_cast<const float4*>(ysrc + (size_t)col0 * DIM);
        #pragma unroll
        for (int idx = tid; idx < BN * 4; idx += BM)
            ys4[idx] = src[idx];
    }
    __syncthreads();
    for (int j = tid; j < BN; j += BM) {
        const float* yr = reinterpret_cast<const float*>(ys4 + j * 4);
        float s = 0.f;
        #pragma unroll
        for (int k = 0; k < DIM; k++) s += yr[k] * yr[k];
        meta[j] = make_float2(s, wsrc[col_w_off + col0 + j] * L2E);
    }
    __syncthreads();

    // this thread's row
    const int r = row0 + tid;
    const float4* xr = reinterpret_cast<const float4*>(p_star + (size_t)r * DIM);
    float xv[DIM];
    #pragma unroll
    for (int k = 0; k < 4; k++) {
        float4 v = xr[k];
        xv[4*k+0] = v.x; xv[4*k+1] = v.y; xv[4*k+2] = v.z; xv[4*k+3] = v.w;
    }
    float xn = 0.f;
    #pragma unroll
    for (int k = 0; k < DIM; k++) xn += xv[k] * xv[k];
    // pre-scale row by -2 into packed regs
    unsigned long long xm2[8];
    #pragma unroll
    for (int k = 0; k < 8; k++)
        xm2[k] = pack2(-2.f * xv[2*k], -2.f * xv[2*k+1]);
    const unsigned long long xn_pack = pack2(xn, 0.f);
    const float rowexp = fast_exp2(wsrc[r] * L2E);

    float acc = 0.f;
    #pragma unroll 4
    for (int j = 0; j < BN; j++) {
        const ulonglong2* yv = reinterpret_cast<const ulonglong2*>(ys4 + j * 4);
        ulonglong2 q0 = yv[0], q1 = yv[1], q2 = yv[2], q3 = yv[3];
        float2 m = meta[j];
        unsigned long long c0 = xn_pack;
        unsigned long long c1 = pack2(m.x, 0.f);
        c0 = fma2(xm2[0], q0.x, c0); c1 = fma2(xm2[1], q0.y, c1);
        c0 = fma2(xm2[2], q1.x, c0); c1 = fma2(xm2[3], q1.y, c1);
        c0 = fma2(xm2[4], q2.x, c0); c1 = fma2(xm2[5], q2.y, c1);
        c0 = fma2(xm2[6], q3.x, c0); c1 = fma2(xm2[7], q3.y, c1);
        float a0, a1, b0, b1;
        unpack2(c0, a0, a1); unpack2(c1, b0, b1);
        float dist2 = (a0 + b0) + (a1 + b1);
        float dist = fast_sqrt(fmaxf(dist2, 0.f));
        float t = fast_exp2(fmaf(dist, -L2E, m.y));
        if (IS_PP && (col0 + j) <= r) t = 0.f;   // strict upper triangle
        acc += t;
    }
    acc *= rowexp;

    float bsum = block_reduce(acc, red);
    if (tid == 0)
        atomicAdd(&g_acc[IS_PP ? 0 : 2], (double)bsum);
}

// Link terms over edges (one thread per edge, both edge sets)
__global__ __launch_bounds__(256) void edge_kernel(
    const float* __restrict__ p_star,
    const float* __restrict__ p,
    const float* __restrict__ a,
    const float* __restrict__ beta,
    const float* __restrict__ gamma,
    const int* __restrict__ e_pp,
    const int* __restrict__ e_ap,
    int E)
{
    __shared__ float red[8];
    int i = blockIdx.x * blockDim.x + threadIdx.x;
    float acc_pp = 0.f, acc_ap = 0.f;
    for (int e = i; e < E; e += gridDim.x * blockDim.x) {
        {
            int s = e_pp[e];
            int t = e_pp[E + e];
            const float4* xs = reinterpret_cast<const float4*>(p_star + (size_t)s * DIM);
            const float4* yt = reinterpret_cast<const float4*>(p + (size_t)t * DIM);
            float d2 = 0.f;
            #pragma unroll
            for (int k = 0; k < 4; k++) {
                float4 xv = xs[k], yv = yt[k];
                float dx = xv.x - yv.x, dy = xv.y - yv.y, dz = xv.z - yv.z, dw = xv.w - yv.w;
                d2 += dx*dx + dy*dy + dz*dz + dw*dw;
            }
            acc_pp += gamma[s] + gamma[t + N_PP] - fast_sqrt(d2);
        }
        {
            int s = e_ap[e];
            int t = e_ap[E + e];           // in [N_PP, N_AP)
            const float4* xs = reinterpret_cast<const float4*>(p_star + (size_t)s * DIM);
            const float4* yt = reinterpret_cast<const float4*>(a + (size_t)(t - N_PP) * DIM);
            float d2 = 0.f;
            #pragma unroll
            for (int k = 0; k < 4; k++) {
                float4 xv = xs[k], yv = yt[k];
                float dx = xv.x - yv.x, dy = xv.y - yv.y, dz = xv.z - yv.z, dw = xv.w - yv.w;
                d2 += dx*dx + dy*dy + dz*dz + dw*dw;
            }
            acc_ap += beta[s] + beta[t] - fast_sqrt(d2);
        }
    }
    float s_pp = block_reduce(acc_pp, red);
    __syncthreads();
    float s_ap = block_reduce(acc_ap, red);
    if (threadIdx.x == 0) {
        atomicAdd(&g_acc[1], (double)s_pp);
        atomicAdd(&g_acc[3], (double)s_ap);
    }
}

__global__ void finalize_kernel(float* out) {
    double nll_pp = -(g_acc[1] - g_acc[0]);
    double nll_ap = -(g_acc[3] - g_acc[2]);
    out[0] = (float)(0.5 * nll_pp / (double)N_PP + 0.5 * nll_ap / (double)N_PP);
}

extern "C" void kernel_launch(void* const* d_in, const int* in_sizes, int n_in,
                              void* d_out, int out_size) {
    const float* p_star = (const float*)d_in[0];
    const float* p      = (const float*)d_in[1];
    const float* a      = (const float*)d_in[2];
    const float* beta   = (const float*)d_in[3];
    const float* gamma  = (const float*)d_in[4];
    const int*   e_pp   = (const int*)d_in[5];
    const int*   e_ap   = (const int*)d_in[6];
    int E = in_sizes[5] / 2;

    zero_acc_kernel<<<1, 32>>>();

    dim3 grid(N_PP / BN, N_PP / BM);   // 64 x 32
    pair_kernel<true ><<<grid, BM>>>(p_star, p, gamma, N_PP);  // pp: col weight gamma[col+N_PP]
    pair_kernel<false><<<grid, BM>>>(p_star, a, beta,  N_PP);  // ap: col weight beta[col+N_PP]

    int eblocks = (E + 255) / 256;
    edge_kernel<<<eblocks, 256>>>(p_star, p, a, beta, gamma, e_pp, e_ap, E);

    finalize_kernel<<<1, 1>>>((float*)d_out);
}

// round 3
// speedup vs baseline: 1.2638x; 1.2536x over previous
#include <cuda_runtime.h>
#include <cuda_bf16.h>

#define N_PP 8192
#define DIM  16
#define L2E  1.4426950408889634f

#define TPB      256          // threads per block
#define ROWS_PT  256          // rows staged per pair tile
#define COLS_PT  512          // cols per pair tile (2 per thread)
#define NB_ROW   (N_PP / ROWS_PT)   // 32
#define NB_COL   (N_PP / COLS_PT)   // 16
#define NB_PAIR  (NB_ROW * NB_COL)  // 512
#define NB_EDGE  128
#define NB_TOTAL (2 * NB_PAIR + NB_EDGE)

// accumulators: 0 = nonlink_pp, 1 = link_pp, 2 = nonlink_ap, 3 = link_ap
__device__ double g_acc[4];
__device__ unsigned int g_arrive;

typedef unsigned long long ull;

__device__ __forceinline__ float fast_sqrt(float x) {
    float r; asm("sqrt.approx.f32 %0, %1;" : "=f"(r) : "f"(x)); return r;
}
__device__ __forceinline__ float fast_exp2(float x) {
    float r; asm("ex2.approx.f32 %0, %1;" : "=f"(r) : "f"(x)); return r;
}
__device__ __forceinline__ ull pack2(float lo, float hi) {
    ull r; asm("mov.b64 %0, {%1, %2};" : "=l"(r) : "f"(lo), "f"(hi)); return r;
}
__device__ __forceinline__ void unpack2(ull v, float& lo, float& hi) {
    asm("mov.b64 {%0, %1}, %2;" : "=f"(lo), "=f"(hi) : "l"(v));
}
__device__ __forceinline__ ull fma2(ull a, ull b, ull c) {
    ull d; asm("fma.rn.f32x2 %0, %1, %2, %3;" : "=l"(d) : "l"(a), "l"(b), "l"(c));
    return d;
}

__device__ __forceinline__ float block_reduce(float v, float* sh) {
    #pragma unroll
    for (int off = 16; off > 0; off >>= 1)
        v += __shfl_down_sync(0xffffffffu, v, off);
    int lane = threadIdx.x & 31;
    int w = threadIdx.x >> 5;
    if (lane == 0) sh[w] = v;
    __syncthreads();
    if (w == 0) {
        v = (lane < (int)(TPB >> 5)) ? sh[lane] : 0.f;
        #pragma unroll
        for (int off = 4; off > 0; off >>= 1)
            v += __shfl_down_sync(0xffffffffu, v, off);
    }
    return v;
}

// pair-tile core: thread owns 2 columns (packed y in regs), rows broadcast
// from smem. Chain init pack2(xn, yn) folds both norms in for free.
template <bool MASKED>
__device__ __forceinline__ void pair_loop(
    const ull* __restrict__ xs,       // smem: ROWS_PT x 8 packed (-2x)
    const float2* __restrict__ xmeta, // smem: (xn, lrow)
    const ull y0[8], const ull y1[8],
    float yn0, float yn1,
    int row0, int j0g, int j1g,
    float& acc0, float& acc1)
{
    #pragma unroll 2
    for (int rr = 0; rr < ROWS_PT; rr++) {
        const ull* xr = xs + rr * 8;
        ull q0 = xr[0], q1 = xr[1], q2 = xr[2], q3 = xr[3];
        ull q4 = xr[4], q5 = xr[5], q6 = xr[6], q7 = xr[7];
        float2 m = xmeta[rr];
        ull c0 = pack2(m.x, yn0);
        ull c1 = pack2(m.x, yn1);
        c0 = fma2(q0, y0[0], c0);  c1 = fma2(q0, y1[0], c1);
        c0 = fma2(q1, y0[1], c0);  c1 = fma2(q1, y1[1], c1);
        c0 = fma2(q2, y0[2], c0);  c1 = fma2(q2, y1[2], c1);
        c0 = fma2(q3, y0[3], c0);  c1 = fma2(q3, y1[3], c1);
        c0 = fma2(q4, y0[4], c0);  c1 = fma2(q4, y1[4], c1);
        c0 = fma2(q5, y0[5], c0);  c1 = fma2(q5, y1[5], c1);
        c0 = fma2(q6, y0[6], c0);  c1 = fma2(q6, y1[6], c1);
        c0 = fma2(q7, y0[7], c0);  c1 = fma2(q7, y1[7], c1);
        float a0, a1, b0, b1;
        unpack2(c0, a0, a1); unpack2(c1, b0, b1);
        float d2_0 = a0 + a1;
        float d2_1 = b0 + b1;
        float t0 = fast_exp2(fmaf(fast_sqrt(fmaxf(d2_0, 0.f)), -L2E, m.y));
        float t1 = fast_exp2(fmaf(fast_sqrt(fmaxf(d2_1, 0.f)), -L2E, m.y));
        if (MASKED) {
            int r = row0 + rr;
            if (j0g <= r) t0 = 0.f;
            if (j1g <= r) t1 = 0.f;
        }
        acc0 += t0;
        acc1 += t1;
    }
}

__global__ __launch_bounds__(TPB) void fused_kernel(
    const float* __restrict__ p_star,
    const float* __restrict__ p,
    const float* __restrict__ a,
    const float* __restrict__ beta,
    const float* __restrict__ gamma,
    const int* __restrict__ e_pp,
    const int* __restrict__ e_ap,
    int E,
    float* __restrict__ out)
{
    __shared__ ull    xs[ROWS_PT * 8];     // -2x rows, packed f32x2 (16KB)
    __shared__ float2 xmeta[ROWS_PT];      // (xn, lrow)  (2KB)
    __shared__ float  red[8];

    const int bid = blockIdx.x;
    const int tid = threadIdx.x;

    if (bid < 2 * NB_PAIR) {
        // ---------------- pair tiles ----------------
        const bool is_pp = (bid < NB_PAIR);
        const int pb = is_pp ? bid : bid - NB_PAIR;
        const int rb = pb / NB_COL;
        const int cb = pb % NB_COL;
        const int row0 = rb * ROWS_PT;
        const int col0 = cb * COLS_PT;

        // pp blocks fully at/below diagonal have no work
        const bool active = !(is_pp && (col0 + COLS_PT - 1) <= row0);

        if (active) {
            // stage row tile: each thread one row
            {
                int r = row0 + tid;
                const float4* xr = reinterpret_cast<const float4*>(p_star + (size_t)r * DIM);
                float4 v0 = xr[0], v1 = xr[1], v2 = xr[2], v3 = xr[3];
                float xn =
                    v0.x*v0.x + v0.y*v0.y + v0.z*v0.z + v0.w*v0.w +
                    v1.x*v1.x + v1.y*v1.y + v1.z*v1.z + v1.w*v1.w +
                    v2.x*v2.x + v2.y*v2.y + v2.z*v2.z + v2.w*v2.w +
                    v3.x*v3.x + v3.y*v3.y + v3.z*v3.z + v3.w*v3.w;
                ull* xd = xs + tid * 8;
                xd[0] = pack2(-2.f*v0.x, -2.f*v0.y);
                xd[1] = pack2(-2.f*v0.z, -2.f*v0.w);
                xd[2] = pack2(-2.f*v1.x, -2.f*v1.y);
                xd[3] = pack2(-2.f*v1.z, -2.f*v1.w);
                xd[4] = pack2(-2.f*v2.x, -2.f*v2.y);
                xd[5] = pack2(-2.f*v2.z, -2.f*v2.w);
                xd[6] = pack2(-2.f*v3.x, -2.f*v3.y);
                xd[7] = pack2(-2.f*v3.z, -2.f*v3.w);
                float wrow = is_pp ? gamma[r] : beta[r];
                xmeta[tid] = make_float2(xn, wrow * L2E);
            }
            __syncthreads();

            // thread's two columns
            const int j0 = col0 + 2 * tid;
            const int j1 = j0 + 1;
            const float* ysrc = is_pp ? p : a;
            ull y0[8], y1[8];
            float yn0, yn1;
            {
                const float4* ya = reinterpret_cast<const float4*>(ysrc + (size_t)j0 * DIM);
                float s0 = 0.f, s1 = 0.f;
                #pragma unroll
                for (int k = 0; k < 4; k++) {
                    float4 v = ya[k];
                    y0[2*k]   = pack2(v.x, v.y);
                    y0[2*k+1] = pack2(v.z, v.w);
                    s0 += v.x*v.x + v.y*v.y + v.z*v.z + v.w*v.w;
                }
                const float4* yb = reinterpret_cast<const float4*>(ysrc + (size_t)j1 * DIM);
                #pragma unroll
                for (int k = 0; k < 4; k++) {
                    float4 v = yb[k];
                    y1[2*k]   = pack2(v.x, v.y);
                    y1[2*k+1] = pack2(v.z, v.w);
                    s1 += v.x*v.x + v.y*v.y + v.z*v.z + v.w*v.w;
                }
                yn0 = s0; yn1 = s1;
            }

            float acc0 = 0.f, acc1 = 0.f;
            const bool straddle = is_pp && (col0 < row0 + ROWS_PT);
            if (straddle)
                pair_loop<true >(xs, xmeta, y0, y1, yn0, yn1, row0, j0, j1, acc0, acc1);
            else
                pair_loop<false>(xs, xmeta, y0, y1, yn0, yn1, row0, j0, j1, acc0, acc1);

            // apply column weight factor exp2(lw_j)
            const float* wcol = is_pp ? gamma : beta;
            acc0 *= fast_exp2(wcol[N_PP + j0] * L2E);
            acc1 *= fast_exp2(wcol[N_PP + j1] * L2E);

            float bsum = block_reduce(acc0 + acc1, red);
            if (tid == 0)
                atomicAdd(&g_acc[is_pp ? 0 : 2], (double)bsum);
        }
    } else {
        // ---------------- edge blocks ----------------
        const int eb = bid - 2 * NB_PAIR;
        float acc_pp = 0.f, acc_ap = 0.f;
        for (int e = eb * TPB + tid; e < E; e += NB_EDGE * TPB) {
            {
                int s = e_pp[e];
                int t = e_pp[E + e];
                const float4* xsrc = reinterpret_cast<const float4*>(p_star + (size_t)s * DIM);
                const float4* yt = reinterpret_cast<const float4*>(p + (size_t)t * DIM);
                float d2 = 0.f;
                #pragma unroll
                for (int k = 0; k < 4; k++) {
                    float4 xv = xsrc[k], yv = yt[k];
                    float dx = xv.x - yv.x, dy = xv.y - yv.y;
                    float dz = xv.z - yv.z, dw = xv.w - yv.w;
                    d2 += dx*dx + dy*dy + dz*dz + dw*dw;
                }
                acc_pp += gamma[s] + gamma[t + N_PP] - fast_sqrt(d2);
            }
            {
                int s = e_ap[e];
                int t = e_ap[E + e];            // in [N_PP, 2*N_PP)
                const float4* xsrc = reinterpret_cast<const float4*>(p_star + (size_t)s * DIM);
                const float4* yt = reinterpret_cast<const float4*>(a + (size_t)(t - N_PP) * DIM);
                float d2 = 0.f;
                #pragma unroll
                for (int k = 0; k < 4; k++) {
                    float4 xv = xsrc[k], yv = yt[k];
                    float dx = xv.x - yv.x, dy = xv.y - yv.y;
                    float dz = xv.z - yv.z, dw = xv.w - yv.w;
                    d2 += dx*dx + dy*dy + dz*dz + dw*dw;
                }
                acc_ap += beta[s] + beta[t] - fast_sqrt(d2);
            }
        }
        float s_pp = block_reduce(acc_pp, red);
        __syncthreads();
        float s_ap = block_reduce(acc_ap, red);
        if (tid == 0) {
            atomicAdd(&g_acc[1], (double)s_pp);
            atomicAdd(&g_acc[3], (double)s_ap);
        }
    }

    // ---------------- arrival + finalize ----------------
    __syncthreads();
    if (tid == 0) {
        __threadfence();
        unsigned old = atomicAdd(&g_arrive, 1u);
        if (old == (unsigned)(NB_TOTAL - 1)) {
            double nll_pp = -(g_acc[1] - g_acc[0]);
            double nll_ap = -(g_acc[3] - g_acc[2]);
            out[0] = (float)(0.5 * nll_pp / (double)N_PP + 0.5 * nll_ap / (double)N_PP);
            g_acc[0] = 0.0; g_acc[1] = 0.0; g_acc[2] = 0.0; g_acc[3] = 0.0;
            g_arrive = 0u;
            __threadfence();
        }
    }
}

extern "C" void kernel_launch(void* const* d_in, const int* in_sizes, int n_in,
                              void* d_out, int out_size) {
    const float* p_star = (const float*)d_in[0];
    const float* p      = (const float*)d_in[1];
    const float* a      = (const float*)d_in[2];
    const float* beta   = (const float*)d_in[3];
    const float* gamma  = (const float*)d_in[4];
    const int*   e_pp   = (const int*)d_in[5];
    const int*   e_ap   = (const int*)d_in[6];
    int E = in_sizes[5] / 2;

    fused_kernel<<<NB_TOTAL, TPB>>>(p_star, p, a, beta, gamma,
                                    e_pp, e_ap, E, (float*)d_out);
}